// round 6
// baseline (speedup 1.0000x reference)
#include <cuda_runtime.h>
#include <cuda_bf16.h>

// SE block: B=32, H=W=56 (HW=3136), C=256, R=16
#define HW     3136
#define CCH    256
#define NB     32
#define NS     49              // hw chunks (units) per batch
#define CHUNK  64              // hw rows per unit
#define NUNIT  (NB * NS)       // 1568 units per role
#define NTOT   (2 * NUNIT)     // 3136 blocks total

// Scratch (__device__ globals; zero-init at load; self-resetting each launch)
__device__ float g_partial[NUNIT * CCH];   // [u][c]
__device__ float g_gate[NB * CCH];
__device__ unsigned g_done[NB];            // pool units completed per batch
__device__ unsigned g_used[NB];            // scale units consumed per batch
__device__ volatile int g_ready[NB];       // gate-published flag

__global__ void __launch_bounds__(256)
k_se(const float* __restrict__ x,
     const float* __restrict__ w1,
     const float* __restrict__ b1,
     const float* __restrict__ w2,
     const float* __restrict__ b2,
     float* __restrict__ out) {
    const int bid = blockIdx.x;
    const int t   = threadIdx.x;
    const int c4  = t & 63;        // float4 channel group (0..63)
    const int ho  = t >> 6;        // hw sub-offset (0..3)

    // ---- interleaved group schedule: P0, P1, S0, P2, S1, ..., P31, S30, S31 ----
    const int o = bid / NS;        // group index 0..63
    const int s = bid - o * NS;    // unit-in-batch 0..48
    int is_pool, b;
    if (o == 0)       { is_pool = 1; b = 0; }
    else if (o == 63) { is_pool = 0; b = 31; }
    else {
        const int p = (o - 1) >> 1;
        if ((o - 1) & 1) { is_pool = 0; b = p; }      // S(p)
        else             { is_pool = 1; b = p + 1; }  // P(p+1)
    }

    const float4* x4 = reinterpret_cast<const float4*>(x);
    float4*       o4 = reinterpret_cast<float4*>(out);
    const size_t base = ((size_t)b * HW + (size_t)s * CHUNK + ho) * (CCH / 4) + c4;

    if (is_pool) {
        // ================= POOL: read unit, accumulate, publish =================
        float4 acc = make_float4(0.f, 0.f, 0.f, 0.f);
#pragma unroll
        for (int k = 0; k < CHUNK; k += 4) {
            float4 v = x4[base + (size_t)k * (CCH / 4)];   // default: allocate in L2
            acc.x += v.x; acc.y += v.y; acc.z += v.z; acc.w += v.w;
        }

        __shared__ float4 sm[256];
        __shared__ int s_flag;
        sm[t] = acc;
        __syncthreads();
        if (t < 64) {
            float4 a = sm[t], e = sm[t + 64], f = sm[t + 128], h = sm[t + 192];
            float4 r = make_float4(a.x + e.x + f.x + h.x,
                                   a.y + e.y + f.y + h.y,
                                   a.z + e.z + f.z + h.z,
                                   a.w + e.w + f.w + h.w);
            reinterpret_cast<float4*>(g_partial)[((size_t)b * NS + s) * (CCH / 4) + t] = r;
        }
        __threadfence();
        __syncthreads();
        if (t == 0) {
            unsigned old = atomicAdd(&g_done[b], 1u);
            s_flag = (old == NS - 1);
        }
        __syncthreads();
        if (!s_flag) return;

        // ---- last pool block of batch b: excitation MLP ----
        __shared__ float s_s[CCH];
        __shared__ float s_h[16];
        __shared__ float s_w1[CCH * 16];
#pragma unroll
        for (int i = t; i < CCH * 16; i += 256) s_w1[i] = w1[i];

        float accm = 0.f;
#pragma unroll
        for (int ss = 0; ss < NS; ss++)
            accm += __ldcg(&g_partial[((size_t)b * NS + ss) * CCH + t]);
        s_s[t] = accm * (1.0f / (float)HW);
        __syncthreads();

        if (t < 16) {
            float h = b1[t];
#pragma unroll 8
            for (int k = 0; k < CCH; k++)
                h = fmaf(s_s[k], s_w1[k * 16 + t], h);
            s_h[t] = fmaxf(h, 0.f);
        }
        __syncthreads();

        float g = b2[t];
#pragma unroll
        for (int j = 0; j < 16; j++)
            g = fmaf(s_h[j], w2[j * CCH + t], g);
        g_gate[b * CCH + t] = 1.f / (1.f + __expf(-g));

        __threadfence();
        __syncthreads();
        if (t == 0) g_ready[b] = 1;
    } else {
        // ================= SCALE: wait for gate, multiply, stream out =================
        if (t == 0) {
            while (g_ready[b] == 0) __nanosleep(64);
        }
        __syncthreads();

        const float* gp = g_gate + b * CCH + 4 * c4;
        float4 g;
        g.x = __ldcg(gp + 0); g.y = __ldcg(gp + 1);
        g.z = __ldcg(gp + 2); g.w = __ldcg(gp + 3);

#pragma unroll
        for (int k = 0; k < CHUNK; k += 4) {
            const size_t idx = base + (size_t)k * (CCH / 4);
            float4 v = __ldcs(&x4[idx]);   // last use of x: evict-first
            v.x *= g.x; v.y *= g.y; v.z *= g.z; v.w *= g.w;
            __stcs(&o4[idx], v);           // streaming store: don't pollute L2
        }

        __threadfence();
        __syncthreads();
        if (t == 0) {
            unsigned old = atomicAdd(&g_used[b], 1u);
            if (old == NS - 1) {           // last consumer: reset for next graph replay
                g_used[b]  = 0;
                g_done[b]  = 0;
                g_ready[b] = 0;
            }
        }
    }
}

extern "C" void kernel_launch(void* const* d_in, const int* in_sizes, int n_in,
                              void* d_out, int out_size) {
    const float* x  = (const float*)d_in[0];
    const float* w1 = (const float*)d_in[1];
    const float* b1 = (const float*)d_in[2];
    const float* w2 = (const float*)d_in[3];
    const float* b2 = (const float*)d_in[4];
    float* out = (float*)d_out;

    k_se<<<NTOT, 256>>>(x, w1, b1, w2, b2, out);
}